// round 9
// baseline (speedup 1.0000x reference)
#include <cuda_runtime.h>
#include <cuda_fp16.h>
#include <cuda_bf16.h>
#include <cstdint>
#include <cstddef>

// Shapes: x[32,64,25,1024], W[25,192,64], A[3,25,25], out[32,64,25,1024]
// Stage 1 (HMMA fp16): Ybuf[c*75 + k*25 + w][jloc] = sum_c' W[w,c*3+k,c'] x[n,c',w,t]
// Stage 2 (HMMA fp16, A hi/lo): out[n,c,v,t] = sum_r A[v,r] * Ybuf[c*75+r][jloc]
// j is chunked into 8 slices of 4096; stage1/stage2 alternate per chunk so the
// 39.3 MB Y chunk buffer stays L2-resident (L2 persists across launches).

#define NB 32
#define CC 64
#define VV 25
#define TT 1024
#define KK 3
#define OO (KK * CC)      /* 192 */
#define NT (NB * TT)      /* 32768 */
#define NTC 4096          /* j chunk size */
#define NCHUNK (NT / NTC) /* 8 */
#define WS1 72            /* stage1 padded row stride (halves) */

typedef unsigned long long u64;

// 39.3 MB fp16 Y chunk buffer, reused across chunks (device-global, no alloc).
__device__ unsigned short g_Yh[(size_t)CC * 75 * NTC];

// ---------------------------------------------------------------------------
// helpers
// ---------------------------------------------------------------------------
__device__ __forceinline__ uint32_t smem_u32(const void* p) {
    uint32_t a;
    asm("{ .reg .u64 t; cvta.to.shared.u64 t, %1; cvt.u32.u64 %0, t; }"
        : "=r"(a) : "l"(p));
    return a;
}
__device__ __forceinline__ void ldm_x4(uint32_t a[4], uint32_t addr) {
    asm volatile("ldmatrix.sync.aligned.m8n8.x4.shared.b16 {%0,%1,%2,%3}, [%4];"
        : "=r"(a[0]), "=r"(a[1]), "=r"(a[2]), "=r"(a[3]) : "r"(addr));
}
__device__ __forceinline__ void ldm_x2t(uint32_t b[2], uint32_t addr) {
    asm volatile("ldmatrix.sync.aligned.m8n8.x2.trans.shared.b16 {%0,%1}, [%2];"
        : "=r"(b[0]), "=r"(b[1]) : "r"(addr));
}
__device__ __forceinline__ void mma_f16(float c[4], const uint32_t a[4],
                                        const uint32_t b[2]) {
    asm volatile("mma.sync.aligned.m16n8k16.row.col.f32.f16.f16.f32 "
        "{%0,%1,%2,%3}, {%4,%5,%6,%7}, {%8,%9}, {%0,%1,%2,%3};"
        : "+f"(c[0]), "+f"(c[1]), "+f"(c[2]), "+f"(c[3])
        : "r"(a[0]), "r"(a[1]), "r"(a[2]), "r"(a[3]), "r"(b[0]), "r"(b[1]));
}

// ---------------------------------------------------------------------------
// Stage 1: per (w, 64-j tile in chunk): D[192,64] = W_w[192,64] @ X_w[64,64]
// ---------------------------------------------------------------------------
__global__ __launch_bounds__(256, 2) void stage1_mma(
    const float* __restrict__ x, const float* __restrict__ Wg, int jbase)
{
    __shared__ __align__(16) __half sW[OO * WS1];   // 192 x 72
    __shared__ __align__(16) __half sX[64 * WS1];   // 64 x 72

    const uint32_t WHs = smem_u32(sW);
    const uint32_t XHs = smem_u32(sX);

    const int tid  = threadIdx.x;
    const int w    = blockIdx.y;
    const int jloc = blockIdx.x * 64;
    const int jg   = jbase + jloc;
    const int n    = jg >> 10;          // tile never crosses n
    const int t0   = jg & 1023;

    // W[w] 192x64 fp32 -> fp16
    {
        const float* wg = Wg + (size_t)w * OO * 64;
        #pragma unroll
        for (int i = 0; i < 24; ++i) {
            int idx = tid + i * 256;
            int o   = idx >> 5;
            int cp  = idx & 31;
            float2 wv = *(const float2*)(wg + (size_t)o * 64 + cp * 2);
            *(__half2*)&sW[o * WS1 + cp * 2] = __floats2half2_rn(wv.x, wv.y);
        }
    }
    // X tile 64(c') x 64(j) fp32 -> fp16
    {
        const float* xb = x + (size_t)n * CC * VV * TT + (size_t)w * TT + t0;
        #pragma unroll
        for (int i = 0; i < 8; ++i) {
            int idx = tid + i * 256;
            int r   = idx >> 5;
            int cp  = idx & 31;
            float2 xv = *(const float2*)(xb + (size_t)r * (VV * TT) + cp * 2);
            *(__half2*)&sX[r * WS1 + cp * 2] = __floats2half2_rn(xv.x, xv.y);
        }
    }
    __syncthreads();

    const int wid = tid >> 5, lane = tid & 31;
    const int m0 = (wid >> 1) * 48, n0 = (wid & 1) * 32;
    const int arow = lane & 15, acolb = (lane >> 4) * 8, brow = lane & 15;

    float acc[3][4][4] = {};

    #pragma unroll
    for (int ks = 0; ks < 4; ++ks) {
        uint32_t Af[3][4], Bf[4][2];
        #pragma unroll
        for (int i = 0; i < 3; ++i)
            ldm_x4(Af[i], WHs + (uint32_t)(((m0 + 16 * i + arow) * WS1
                                            + ks * 16 + acolb) * 2));
        #pragma unroll
        for (int t = 0; t < 4; ++t)
            ldm_x2t(Bf[t], XHs + (uint32_t)(((ks * 16 + brow) * WS1
                                             + n0 + 8 * t) * 2));
        #pragma unroll
        for (int i = 0; i < 3; ++i)
            #pragma unroll
            for (int t = 0; t < 4; ++t)
                mma_f16(acc[i][t], Af[i], Bf[t]);
    }
    __syncthreads();

    // stage D[o, jloc] as fp16 in the sW region
    {
        const int r = lane >> 2, q = lane & 3;
        #pragma unroll
        for (int i = 0; i < 3; ++i)
            #pragma unroll
            for (int t = 0; t < 4; ++t) {
                int row = m0 + 16 * i + r;
                int col = n0 + 8 * t + 2 * q;
                *(half2*)((char*)sW + (row * WS1 + col) * 2) =
                    __floats2half2_rn(acc[i][t][0], acc[i][t][1]);
                *(half2*)((char*)sW + ((row + 8) * WS1 + col) * 2) =
                    __floats2half2_rn(acc[i][t][2], acc[i][t][3]);
            }
    }
    __syncthreads();

    // copy out: Ybuf row = c*75 + k*25 + w, col jloc (chunk-local)
    #pragma unroll
    for (int i = 0; i < 24; ++i) {
        int idx = tid + i * 256;
        int row = idx >> 5;
        int u   = idx & 31;
        uint32_t val = *(uint32_t*)((char*)sW + row * (WS1 * 2) + u * 4);
        int cch = row / 3;
        int kk  = row - 3 * cch;
        size_t yrow = (size_t)(cch * 75 + kk * VV + w);
        *(uint32_t*)((char*)g_Yh + (yrow * NTC + jloc) * 2 + u * 4) = val;
    }
}

// ---------------------------------------------------------------------------
// Stage 2 (HMMA): out[v, (c,j)] = sum_r Agraph[v,r] * Ybuf[c*75+r][jloc]
// ---------------------------------------------------------------------------
#define JT  128
#define AST 88
#define YST 136

__global__ __launch_bounds__(256) void stage2_mma(
    const float* __restrict__ Ag, float* __restrict__ out, int jbase)
{
    __shared__ __align__(16) __half sAh[32 * AST];
    __shared__ __align__(16) __half sAl[32 * AST];
    __shared__ __align__(16) __half sY[80 * YST];

    const uint32_t AH = smem_u32(sAh);
    const uint32_t AL = smem_u32(sAl);
    const uint32_t YS = smem_u32(sY);

    const int tid  = threadIdx.x;
    const int jloc = blockIdx.x * JT;
    const int c0   = blockIdx.y * 8;
    const int jg   = jbase + jloc;
    const int n    = jg >> 10;
    const int tt0  = jg & 1023;

    // Build graph-A hi/lo fp16 (zero-padded).
    for (int i = tid; i < 80 * 32; i += 256) {
        int r = i >> 5;
        int v = i & 31;
        float a = (r < 75 && v < 25) ? Ag[r * 25 + v] : 0.0f;
        __half h = __float2half_rn(a);
        __half l = __float2half_rn(a - __half2float(h));
        sAh[v * AST + r] = h;
        sAl[v * AST + r] = l;
    }

    const int wid  = tid >> 5, lane = tid & 31;
    const int jw   = wid * 16;
    const int arow = lane & 15, acolb = (lane >> 4) * 8;
    const int brow = lane & 15;
    const int r4   = lane >> 2, q2 = (lane & 3) * 2;

    int lr[5], lch[5];
    #pragma unroll
    for (int s = 0; s < 5; ++s) {
        int i = tid + s * 256;
        lr[s]  = i >> 4;
        lch[s] = i & 15;
    }

    uint4 pf[5];
    {
        const char* yb = (const char*)g_Yh + ((size_t)c0 * 75 * NTC + jloc) * 2;
        #pragma unroll
        for (int s = 0; s < 5; ++s)
            pf[s] = (lr[s] < 75)
                ? *(const uint4*)(yb + (size_t)lr[s] * NTC * 2 + lch[s] * 16)
                : make_uint4(0u, 0u, 0u, 0u);
    }
    __syncthreads();
    #pragma unroll
    for (int s = 0; s < 5; ++s)
        *(uint4*)((char*)sY + (lr[s] * YST + lch[s] * 8) * 2) = pf[s];
    __syncthreads();

    for (int ci = 0; ci < 8; ++ci) {
        const int c = c0 + ci;

        if (ci < 7) {
            const char* yb = (const char*)g_Yh
                           + ((size_t)(c + 1) * 75 * NTC + jloc) * 2;
            #pragma unroll
            for (int s = 0; s < 5; ++s)
                pf[s] = (lr[s] < 75)
                    ? *(const uint4*)(yb + (size_t)lr[s] * NTC * 2 + lch[s] * 16)
                    : make_uint4(0u, 0u, 0u, 0u);
        }

        float acc[2][2][4] = {};
        #pragma unroll
        for (int ks = 0; ks < 5; ++ks) {
            uint32_t ah0[4], ah1[4], al0[4], al1[4], b0[2], b1[2];
            uint32_t aoff0 = (uint32_t)(((arow)      * AST + ks * 16 + acolb) * 2);
            uint32_t aoff1 = (uint32_t)(((16 + arow) * AST + ks * 16 + acolb) * 2);
            ldm_x4(ah0, AH + aoff0);
            ldm_x4(ah1, AH + aoff1);
            ldm_x4(al0, AL + aoff0);
            ldm_x4(al1, AL + aoff1);
            uint32_t boff = (uint32_t)(((ks * 16 + brow) * YST + jw) * 2);
            ldm_x2t(b0, YS + boff);
            ldm_x2t(b1, YS + boff + 16);

            mma_f16(acc[0][0], ah0, b0);  mma_f16(acc[0][0], al0, b0);
            mma_f16(acc[0][1], ah0, b1);  mma_f16(acc[0][1], al0, b1);
            mma_f16(acc[1][0], ah1, b0);  mma_f16(acc[1][0], al1, b0);
            mma_f16(acc[1][1], ah1, b1);  mma_f16(acc[1][1], al1, b1);
        }

        float* ob = out + (((size_t)n * CC + c) * VV) * TT + tt0;
        #pragma unroll
        for (int m = 0; m < 2; ++m)
            #pragma unroll
            for (int t = 0; t < 2; ++t) {
                int v0 = m * 16 + r4;
                int jc = jw + t * 8 + q2;
                if (v0 < VV)
                    *(float2*)(ob + (size_t)v0 * TT + jc) =
                        make_float2(acc[m][t][0], acc[m][t][1]);
                int v1 = v0 + 8;
                if (v1 < VV)
                    *(float2*)(ob + (size_t)v1 * TT + jc) =
                        make_float2(acc[m][t][2], acc[m][t][3]);
            }

        if (ci < 7) {
            __syncthreads();
            #pragma unroll
            for (int s = 0; s < 5; ++s)
                *(uint4*)((char*)sY + (lr[s] * YST + lch[s] * 8) * 2) = pf[s];
            __syncthreads();
        }
    }
}

// ---------------------------------------------------------------------------
extern "C" void kernel_launch(void* const* d_in, const int* in_sizes, int n_in,
                              void* d_out, int out_size)
{
    const float* x  = (const float*)d_in[0];
    const float* Wg = (const float*)d_in[1];
    const float* Ag = (const float*)d_in[2];
    float* out = (float*)d_out;

    // Interleave stage1/stage2 per j-chunk; stream order serializes them and
    // the 39.3 MB Y chunk buffer stays L2-resident between the paired launches.
    for (int ch = 0; ch < NCHUNK; ++ch) {
        dim3 g1(NTC / 64, VV);        // (64, 25)
        stage1_mma<<<g1, 256>>>(x, Wg, ch * NTC);
        dim3 g2(NTC / JT, 8);         // (32, 8)
        stage2_mma<<<g2, 256>>>(Ag, out, ch * NTC);
    }
}